// round 4
// baseline (speedup 1.0000x reference)
#include <cuda_runtime.h>

#define FULLMASK 0xffffffffu

// Problem dims (fixed by the dataset)
#define Bb 16
#define Ss 256
#define Nn 16
#define Dd 6
#define Hh 16
#define CHAINS (Bb * Nn)   // 256
#define HW (Hh * 32)       // 512

// Scratch for all rotor states: [chain][t][h*32+blade] = 128 MB
__device__ float g_psi[(size_t)CHAINS * Ss * HW];

// rsqrt(sum over head of v^2 + 1e-8): 4 local regs + 8-lane group reduce
__device__ __forceinline__ float qnorm8(const float v0, const float v1,
                                        const float v2, const float v3) {
    float s = v0 * v0 + v1 * v1;
    s = fmaf(v2, v2, s);
    s = fmaf(v3, v3, s);
    s += __shfl_xor_sync(FULLMASK, s, 1);
    s += __shfl_xor_sync(FULLMASK, s, 2);
    s += __shfl_xor_sync(FULLMASK, s, 4);
    s += 1e-8f;
    float r = rsqrtf(s);
    r = r * (1.5f - 0.5f * s * r * r);   // one NR step for 256-step stability
    return r;
}

// ---------------------------------------------------------------------------
// Phase 1: rotor recurrence. 8 lanes per head (4 blades/lane), 4 heads/warp.
// 1024 warps, launched as ONE wave (128 blocks x 256 threads).
//
// Math note: delta_r normalization is elided — GP is bilinear, so the scale
// factor of u is absorbed by the outer normalization (deviation ~1e-8 via eps).
// ---------------------------------------------------------------------------
__global__ void __launch_bounds__(256) rotor_rnn_kernel(
    const float* __restrict__ x,      // [B,S,N,D]
    const float* __restrict__ W_in,   // [D, H*32]
    const float* __restrict__ b_in)   // [H*32]
{
    const int gw   = (blockIdx.x * blockDim.x + threadIdx.x) >> 5;  // 0..1023
    const int lane = threadIdx.x & 31;
    const int c  = gw >> 2;           // chain 0..255
    const int hq = gw & 3;            // head quad within chain
    const int w  = lane >> 3;         // head within quad
    const int g  = lane & 7;          // blade group (blades g*4 .. g*4+3)
    const int h  = hq * 4 + w;
    const int b  = c >> 4;
    const int n  = c & (Nn - 1);
    const int col0 = h * 32 + g * 4;

    // W_in columns + bias for this lane's 4 blades
    float wi[4][Dd];
    float bi[4];
#pragma unroll
    for (int r = 0; r < 4; ++r) {
#pragma unroll
        for (int d = 0; d < Dd; ++d) wi[r][d] = __ldg(W_in + d * HW + col0 + r);
        bi[r] = __ldg(b_in + col0 + r);
    }

    // Per-(lane, mask) sigma sign: sigma = G0*(m1^m2) ^ G1*m2, G = g^m
    unsigned sm8[8];
#pragma unroll
    for (int m = 0; m < 8; ++m) {
        unsigned G  = (unsigned)(g ^ m);
        unsigned m1 = (m >> 1) & 1u, m2 = (m >> 2) & 1u;
        unsigned sgn = ((G & 1u) & (m1 ^ m2)) ^ (((G >> 1) & 1u) & m2);
        sm8[m] = sgn << 31;
    }

    // psi0 = identity rotor (blade 0 lives at g==0, r==0)
    float ps0 = (g == 0) ? 1.0f : 0.0f, ps1 = 0.f, ps2 = 0.f, ps3 = 0.f;

    const float* xp = x + ((size_t)(b * Ss) * Nn + n) * Dd;
    float4* pp = (float4*)(g_psi + ((size_t)c * Ss) * HW + col0);

    float cx[Dd];
#pragma unroll
    for (int d = 0; d < Dd; ++d) cx[d] = __ldg(xp + d);

    for (int t = 0; t < Ss; ++t) {
        // prefetch next x (warp-uniform broadcast)
        const float* xn = xp + Nn * Dd;
        const bool more = (t + 1 < Ss);
        float nx[Dd];
#pragma unroll
        for (int d = 0; d < Dd; ++d) nx[d] = more ? __ldg(xn + d) : 0.0f;

        // u = x_t @ W_in + b_in ; +1 on blade 0.  (NO normalization: elided.)
        float dl0, dl1, dl2, dl3;
        {
            float a0 = bi[0], a1 = bi[1], a2 = bi[2], a3 = bi[3];
#pragma unroll
            for (int d = 0; d < Dd; ++d) {
                a0 = fmaf(wi[0][d], cx[d], a0);
                a1 = fmaf(wi[1][d], cx[d], a1);
                a2 = fmaf(wi[2][d], cx[d], a2);
                a3 = fmaf(wi[3][d], cx[d], a3);
            }
            if (g == 0) a0 += 1.0f;
            dl0 = a0; dl1 = a1; dl2 = a2; dl3 = a3;
        }

        // geometric product (two accumulator banks for ILP)
        float pA0, pA1, pA2, pA3;
        float pB0 = 0.f, pB1 = 0.f, pB2 = 0.f, pB3 = 0.f;

        // ---- m = 0: ps is LOCAL (shfl_xor 0 identity), sigma = 0, P = 0 ----
        {
            float a0 = __shfl_sync(FULLMASK, dl0, 0, 8);
            float a1 = __shfl_sync(FULLMASK, dl1, 0, 8);
            float a2 = __shfl_sync(FULLMASK, dl2, 0, 8);
            float a3 = __shfl_sync(FULLMASK, dl3, 0, 8);
            // jr = 0
            pA0 = a0 * ps0; pA1 = a1 * ps0; pA2 = a2 * ps0; pA3 = a3 * ps0;
            // jr = 1 (P==0): +a1,+a0,-a3,-a2
            pA0 = fmaf( a1, ps1, pA0);
            pA1 = fmaf( a0, ps1, pA1);
            pA2 = fmaf(-a3, ps1, pA2);
            pA3 = fmaf(-a2, ps1, pA3);
            // jr = 2 (P==0): +a2,+a3,+a0,+a1
            pA0 = fmaf( a2, ps2, pA0);
            pA1 = fmaf( a3, ps2, pA1);
            pA2 = fmaf( a0, ps2, pA2);
            pA3 = fmaf( a1, ps2, pA3);
            // jr = 3: -a3,-a2,+a1,+a0
            pA0 = fmaf(-a3, ps3, pA0);
            pA1 = fmaf(-a2, ps3, pA1);
            pA2 = fmaf( a1, ps3, pA2);
            pA3 = fmaf( a0, ps3, pA3);
        }

        // ---- m = 1..7 ----
#pragma unroll
        for (int m = 1; m < 8; ++m) {
            float pm0 = __shfl_xor_sync(FULLMASK, ps0, m);
            float pm1 = __shfl_xor_sync(FULLMASK, ps1, m);
            float pm2 = __shfl_xor_sync(FULLMASK, ps2, m);
            float pm3 = __shfl_xor_sync(FULLMASK, ps3, m);
            unsigned sg = sm8[m];
            float a0 = __uint_as_float(__float_as_uint(__shfl_sync(FULLMASK, dl0, m, 8)) ^ sg);
            float a1 = __uint_as_float(__float_as_uint(__shfl_sync(FULLMASK, dl1, m, 8)) ^ sg);
            float a2 = __uint_as_float(__float_as_uint(__shfl_sync(FULLMASK, dl2, m, 8)) ^ sg);
            float a3 = __uint_as_float(__float_as_uint(__shfl_sync(FULLMASK, dl3, m, 8)) ^ sg);

            const unsigned P = ((m) ^ (m >> 1) ^ (m >> 2)) & 1u;
            float& q0 = (m & 1) ? pB0 : pA0;
            float& q1 = (m & 1) ? pB1 : pA1;
            float& q2 = (m & 1) ? pB2 : pA2;
            float& q3 = (m & 1) ? pB3 : pA3;

            // jr = 0: sign +
            q0 = fmaf(a0, pm0, q0);
            q1 = fmaf(a1, pm0, q1);
            q2 = fmaf(a2, pm0, q2);
            q3 = fmaf(a3, pm0, q3);
            // jr = 1: neg = kr1 ^ P
            if (P == 0) {
                q0 = fmaf( a1, pm1, q0);
                q1 = fmaf( a0, pm1, q1);
                q2 = fmaf(-a3, pm1, q2);
                q3 = fmaf(-a2, pm1, q3);
            } else {
                q0 = fmaf(-a1, pm1, q0);
                q1 = fmaf(-a0, pm1, q1);
                q2 = fmaf( a3, pm1, q2);
                q3 = fmaf( a2, pm1, q3);
            }
            // jr = 2: neg = P
            if (P == 0) {
                q0 = fmaf( a2, pm2, q0);
                q1 = fmaf( a3, pm2, q1);
                q2 = fmaf( a0, pm2, q2);
                q3 = fmaf( a1, pm2, q3);
            } else {
                q0 = fmaf(-a2, pm2, q0);
                q1 = fmaf(-a3, pm2, q1);
                q2 = fmaf(-a0, pm2, q2);
                q3 = fmaf(-a1, pm2, q3);
            }
            // jr = 3: neg = kr1^1 (P-independent)
            q0 = fmaf(-a3, pm3, q0);
            q1 = fmaf(-a2, pm3, q1);
            q2 = fmaf( a1, pm3, q2);
            q3 = fmaf( a0, pm3, q3);
        }
        float pn0 = pA0 + pB0, pn1 = pA1 + pB1, pn2 = pA2 + pB2, pn3 = pA3 + pB3;

        // psi = normalize(pn)
        float rn = qnorm8(pn0, pn1, pn2, pn3);
        ps0 = pn0 * rn; ps1 = pn1 * rn; ps2 = pn2 * rn; ps3 = pn3 * rn;

        *pp = make_float4(ps0, ps1, ps2, ps3);   // one STG.128/lane, coalesced
        pp += HW / 4;
        xp = xn;
#pragma unroll
        for (int d = 0; d < Dd; ++d) cx[d] = nx[d];
    }
}

// ---------------------------------------------------------------------------
// Phase 2: y[b,t,n,:] = x[b,t,n,:] + psi_row @ W_out + b_out
// W_out in registers (96/lane); psi as float4 with next-row double buffering
// (MLP 8). 4096 warps x 16 contiguous rows each.
// ---------------------------------------------------------------------------
__global__ void __launch_bounds__(256) proj_kernel(
    const float* __restrict__ x,      // [B,S,N,D]
    const float* __restrict__ W_out,  // [H*32, D]
    const float* __restrict__ b_out,  // [D]
    float* __restrict__ y)            // [B,S,N,D]
{
    const int warpId = (blockIdx.x * blockDim.x + threadIdx.x) >> 5;  // 0..4095
    const int lane   = threadIdx.x & 31;

    // This lane's 16 W_out columns: cc = k*128 + lane*4 + q
    float wv[16][Dd];
#pragma unroll
    for (int k = 0; k < 4; ++k)
#pragma unroll
        for (int q = 0; q < 4; ++q) {
            const int cc = k * 128 + lane * 4 + q;
#pragma unroll
            for (int d = 0; d < Dd; ++d)
                wv[k * 4 + q][d] = __ldg(W_out + cc * Dd + d);
        }
    const float bo = (lane < Dd) ? __ldg(b_out + lane) : 0.0f;

    const int row0 = warpId * 16;
    const float4* pr = (const float4*)(g_psi + (size_t)row0 * HW) + lane;

    float4 p0 = __ldg(pr +  0);
    float4 p1 = __ldg(pr + 32);
    float4 p2 = __ldg(pr + 64);
    float4 p3 = __ldg(pr + 96);

    for (int rr = 0; rr < 16; ++rr) {
        // prefetch next row while we compute (keeps 8 LDG.128 in flight)
        float4 n0, n1, n2, n3;
        if (rr + 1 < 16) {
            const float4* prn = pr + 128;
            n0 = __ldg(prn +  0);
            n1 = __ldg(prn + 32);
            n2 = __ldg(prn + 64);
            n3 = __ldg(prn + 96);
        } else {
            n0 = n1 = n2 = n3 = make_float4(0.f, 0.f, 0.f, 0.f);
        }

        float a0 = 0.f, a1 = 0.f, a2 = 0.f, a3 = 0.f, a4 = 0.f, a5 = 0.f;
        const float4 pk[4] = {p0, p1, p2, p3};
#pragma unroll
        for (int k = 0; k < 4; ++k) {
            const float4 p = pk[k];
            const float* wp0 = wv[k * 4 + 0];
            const float* wp1 = wv[k * 4 + 1];
            const float* wp2 = wv[k * 4 + 2];
            const float* wp3 = wv[k * 4 + 3];
            a0 = fmaf(p.x, wp0[0], a0); a1 = fmaf(p.x, wp0[1], a1);
            a2 = fmaf(p.x, wp0[2], a2); a3 = fmaf(p.x, wp0[3], a3);
            a4 = fmaf(p.x, wp0[4], a4); a5 = fmaf(p.x, wp0[5], a5);
            a0 = fmaf(p.y, wp1[0], a0); a1 = fmaf(p.y, wp1[1], a1);
            a2 = fmaf(p.y, wp1[2], a2); a3 = fmaf(p.y, wp1[3], a3);
            a4 = fmaf(p.y, wp1[4], a4); a5 = fmaf(p.y, wp1[5], a5);
            a0 = fmaf(p.z, wp2[0], a0); a1 = fmaf(p.z, wp2[1], a1);
            a2 = fmaf(p.z, wp2[2], a2); a3 = fmaf(p.z, wp2[3], a3);
            a4 = fmaf(p.z, wp2[4], a4); a5 = fmaf(p.z, wp2[5], a5);
            a0 = fmaf(p.w, wp3[0], a0); a1 = fmaf(p.w, wp3[1], a1);
            a2 = fmaf(p.w, wp3[2], a2); a3 = fmaf(p.w, wp3[3], a3);
            a4 = fmaf(p.w, wp3[4], a4); a5 = fmaf(p.w, wp3[5], a5);
        }
#pragma unroll
        for (int o = 16; o; o >>= 1) {
            a0 += __shfl_xor_sync(FULLMASK, a0, o);
            a1 += __shfl_xor_sync(FULLMASK, a1, o);
            a2 += __shfl_xor_sync(FULLMASK, a2, o);
            a3 += __shfl_xor_sync(FULLMASK, a3, o);
            a4 += __shfl_xor_sync(FULLMASK, a4, o);
            a5 += __shfl_xor_sync(FULLMASK, a5, o);
        }

        const int row = row0 + rr;                 // chain*256 + t
        const int c = row >> 8;
        const int t = row & (Ss - 1);
        const int b = c >> 4;
        const int n = c & (Nn - 1);
        const size_t off = (((size_t)b * Ss + t) * Nn + n) * Dd;
        if (lane < Dd) {
            float av = (lane == 0) ? a0 : (lane == 1) ? a1 : (lane == 2) ? a2
                     : (lane == 3) ? a3 : (lane == 4) ? a4 : a5;
            y[off + lane] = x[off + lane] + av + bo;
        }

        p0 = n0; p1 = n1; p2 = n2; p3 = n3;
        pr += 128;
    }
}

extern "C" void kernel_launch(void* const* d_in, const int* in_sizes, int n_in,
                              void* d_out, int out_size) {
    const float* x     = (const float*)d_in[0];
    const float* W_in  = (const float*)d_in[1];
    const float* b_in  = (const float*)d_in[2];
    const float* W_out = (const float*)d_in[3];
    const float* b_out = (const float*)d_in[4];
    float* y = (float*)d_out;

    // Phase 1: 1024 warps in ONE wave (128 blocks x 8 warps)
    rotor_rnn_kernel<<<128, 256>>>(x, W_in, b_in);
    // Phase 2: 4096 warps x 16 rows = 65536 output rows
    proj_kernel<<<512, 256>>>(x, W_out, b_out, y);
}

// round 5
// speedup vs baseline: 1.3986x; 1.3986x over previous
#include <cuda_runtime.h>

#define FULLMASK 0xffffffffu

// Problem dims (fixed by the dataset)
#define Bb 16
#define Ss 256
#define Nn 16
#define Dd 6
#define Hh 16
#define CHAINS (Bb * Nn)   // 256
#define HW (Hh * 32)       // 512

// Per-(row, head) projection partials: [c*256+t][16 heads * 6] = 25 MB
__device__ float g_part[(size_t)CHAINS * Ss * 96];

// sign of blade product e_a * e_b in Cl(5,0), matches reference Cayley
__device__ __forceinline__ int clifford_sign_neg(unsigned a, unsigned b) {
    a >>= 1;
    unsigned s = 0;
    while (a) { s += __popc(a & b); a >>= 1; }
    return (int)(s & 1u);
}

// ---------------------------------------------------------------------------
// Phase 1: rotor recurrence + fused output projection.
// 8 lanes per head (4 blades/lane), 4 heads/warp, 1024 warps.
//
// Recurrence carries the UNNORMALIZED product w_t:
//   w_t = GP(u_t * rn_{t-2}, w_{t-1})          (norm OFF the critical path)
//   psi_t = w_t * rsqrt(|w_t|^2 + 1e-12)       (exact normalize for output)
// Bilinearity of GP makes this identical to the reference up to O(1e-8) eps
// terms. The stale scale rn_{t-2} keeps |w| bounded (oscillatory, ~e^±5).
//
// Projection partials (per head): part[d] = sum_r psi[col0+r][d]*W_out, then
// an 8-lane butterfly reduce; lanes g<6 store head-sums to g_part.
// ---------------------------------------------------------------------------
__global__ void __launch_bounds__(256) rotor_rnn_kernel(
    const float* __restrict__ x,      // [B,S,N,D]
    const float* __restrict__ W_in,   // [D, H*32]
    const float* __restrict__ b_in,   // [H*32]
    const float* __restrict__ W_out)  // [H*32, D]
{
    const int gw   = (blockIdx.x * blockDim.x + threadIdx.x) >> 5;  // 0..1023
    const int lane = threadIdx.x & 31;
    const int c  = gw >> 2;           // chain 0..255
    const int hq = gw & 3;            // head quad within chain
    const int w  = lane >> 3;         // head within quad
    const int g  = lane & 7;          // blade group (blades g*4 .. g*4+3)
    const int h  = hq * 4 + w;
    const int b  = c >> 4;
    const int n  = c & (Nn - 1);
    const int col0 = h * 32 + g * 4;

    // W_in columns + bias for this lane's 4 blades
    float wi[4][Dd];
    float bi[4];
#pragma unroll
    for (int r = 0; r < 4; ++r) {
#pragma unroll
        for (int d = 0; d < Dd; ++d) wi[r][d] = __ldg(W_in + d * HW + col0 + r);
        bi[r] = __ldg(b_in + col0 + r);
    }

    // W_out rows for this lane's 4 blades
    float wo[4][Dd];
#pragma unroll
    for (int r = 0; r < 4; ++r)
#pragma unroll
        for (int d = 0; d < Dd; ++d) wo[r][d] = __ldg(W_out + (col0 + r) * Dd + d);

    // Per-(lane, mask) sigma sign: sigma = G0*(m1^m2) ^ G1*m2, G = g^m
    unsigned sm8[8];
#pragma unroll
    for (int m = 0; m < 8; ++m) {
        unsigned G  = (unsigned)(g ^ m);
        unsigned m1 = (m >> 1) & 1u, m2 = (m >> 2) & 1u;
        unsigned sgn = ((G & 1u) & (m1 ^ m2)) ^ (((G >> 1) & 1u) & m2);
        sm8[m] = sgn << 31;
    }

    // state: unnormalized carrier (init = identity rotor, |.|=1)
    float w0 = (g == 0) ? 1.0f : 0.0f, w1 = 0.f, w2 = 0.f, w3 = 0.f;
    float rnA = 1.0f;   // rn_{t-2}
    float rnB = 1.0f;   // rn_{t-1}

    const float* xp = x + ((size_t)(b * Ss) * Nn + n) * Dd;
    float* pw = g_part + ((size_t)c * Ss) * 96 + hq * 24 + w * 6 + g;

    float cx[Dd];
#pragma unroll
    for (int d = 0; d < Dd; ++d) cx[d] = __ldg(xp + d);

    for (int t = 0; t < Ss; ++t) {
        // prefetch next x (warp-uniform broadcast)
        const float* xn = xp + Nn * Dd;
        const bool more = (t + 1 < Ss);
        float nx[Dd];
#pragma unroll
        for (int d = 0; d < Dd; ++d) nx[d] = more ? __ldg(xn + d) : 0.0f;

        // u = x_t @ W_in + b_in ; +1 on blade 0 ; scaled by stale rn_{t-2}.
        float dl0, dl1, dl2, dl3;
        {
            float a0 = bi[0], a1 = bi[1], a2 = bi[2], a3 = bi[3];
#pragma unroll
            for (int d = 0; d < Dd; ++d) {
                a0 = fmaf(wi[0][d], cx[d], a0);
                a1 = fmaf(wi[1][d], cx[d], a1);
                a2 = fmaf(wi[2][d], cx[d], a2);
                a3 = fmaf(wi[3][d], cx[d], a3);
            }
            if (g == 0) a0 += 1.0f;
            dl0 = a0 * rnA; dl1 = a1 * rnA; dl2 = a2 * rnA; dl3 = a3 * rnA;
        }

        // geometric product (two accumulator banks for ILP)
        float pA0, pA1, pA2, pA3;
        float pB0 = 0.f, pB1 = 0.f, pB2 = 0.f, pB3 = 0.f;

        // ---- m = 0: ps is LOCAL, sigma = 0, P = 0 ----
        {
            float a0 = __shfl_sync(FULLMASK, dl0, 0, 8);
            float a1 = __shfl_sync(FULLMASK, dl1, 0, 8);
            float a2 = __shfl_sync(FULLMASK, dl2, 0, 8);
            float a3 = __shfl_sync(FULLMASK, dl3, 0, 8);
            pA0 = a0 * w0; pA1 = a1 * w0; pA2 = a2 * w0; pA3 = a3 * w0;
            pA0 = fmaf( a1, w1, pA0);
            pA1 = fmaf( a0, w1, pA1);
            pA2 = fmaf(-a3, w1, pA2);
            pA3 = fmaf(-a2, w1, pA3);
            pA0 = fmaf( a2, w2, pA0);
            pA1 = fmaf( a3, w2, pA1);
            pA2 = fmaf( a0, w2, pA2);
            pA3 = fmaf( a1, w2, pA3);
            pA0 = fmaf(-a3, w3, pA0);
            pA1 = fmaf(-a2, w3, pA1);
            pA2 = fmaf( a1, w3, pA2);
            pA3 = fmaf( a0, w3, pA3);
        }

        // ---- m = 1..7 ----
#pragma unroll
        for (int m = 1; m < 8; ++m) {
            float pm0 = __shfl_xor_sync(FULLMASK, w0, m);
            float pm1 = __shfl_xor_sync(FULLMASK, w1, m);
            float pm2 = __shfl_xor_sync(FULLMASK, w2, m);
            float pm3 = __shfl_xor_sync(FULLMASK, w3, m);
            unsigned sg = sm8[m];
            float a0 = __uint_as_float(__float_as_uint(__shfl_sync(FULLMASK, dl0, m, 8)) ^ sg);
            float a1 = __uint_as_float(__float_as_uint(__shfl_sync(FULLMASK, dl1, m, 8)) ^ sg);
            float a2 = __uint_as_float(__float_as_uint(__shfl_sync(FULLMASK, dl2, m, 8)) ^ sg);
            float a3 = __uint_as_float(__float_as_uint(__shfl_sync(FULLMASK, dl3, m, 8)) ^ sg);

            const unsigned P = ((m) ^ (m >> 1) ^ (m >> 2)) & 1u;
            float& q0 = (m & 1) ? pB0 : pA0;
            float& q1 = (m & 1) ? pB1 : pA1;
            float& q2 = (m & 1) ? pB2 : pA2;
            float& q3 = (m & 1) ? pB3 : pA3;

            // jr = 0: +
            q0 = fmaf(a0, pm0, q0);
            q1 = fmaf(a1, pm0, q1);
            q2 = fmaf(a2, pm0, q2);
            q3 = fmaf(a3, pm0, q3);
            // jr = 1: neg = kr1 ^ P
            if (P == 0) {
                q0 = fmaf( a1, pm1, q0);
                q1 = fmaf( a0, pm1, q1);
                q2 = fmaf(-a3, pm1, q2);
                q3 = fmaf(-a2, pm1, q3);
            } else {
                q0 = fmaf(-a1, pm1, q0);
                q1 = fmaf(-a0, pm1, q1);
                q2 = fmaf( a3, pm1, q2);
                q3 = fmaf( a2, pm1, q3);
            }
            // jr = 2: neg = P
            if (P == 0) {
                q0 = fmaf( a2, pm2, q0);
                q1 = fmaf( a3, pm2, q1);
                q2 = fmaf( a0, pm2, q2);
                q3 = fmaf( a1, pm2, q3);
            } else {
                q0 = fmaf(-a2, pm2, q0);
                q1 = fmaf(-a3, pm2, q1);
                q2 = fmaf(-a0, pm2, q2);
                q3 = fmaf(-a1, pm2, q3);
            }
            // jr = 3: neg = kr1^1 (P-independent)
            q0 = fmaf(-a3, pm3, q0);
            q1 = fmaf(-a2, pm3, q1);
            q2 = fmaf( a1, pm3, q2);
            q3 = fmaf( a0, pm3, q3);
        }
        // new raw state
        float nw0 = pA0 + pB0, nw1 = pA1 + pB1, nw2 = pA2 + pB2, nw3 = pA3 + pB3;

        // ---- everything below is OFF the recurrence critical path ----
        // exact normalization for the OUTPUT value
        float s = nw0 * nw0 + nw1 * nw1;
        s = fmaf(nw2, nw2, s);
        s = fmaf(nw3, nw3, s);
        s += __shfl_xor_sync(FULLMASK, s, 1);
        s += __shfl_xor_sync(FULLMASK, s, 2);
        s += __shfl_xor_sync(FULLMASK, s, 4);
        s += 1e-12f;
        float rn = rsqrtf(s);
        rn = rn * (1.5f - 0.5f * s * rn * rn);   // one NR step
        float st0 = nw0 * rn, st1 = nw1 * rn, st2 = nw2 * rn, st3 = nw3 * rn;

        // projection partials for this lane's 4 columns
        float p0, p1, p2, p3, p4, p5;
        p0 = st0 * wo[0][0]; p1 = st0 * wo[0][1]; p2 = st0 * wo[0][2];
        p3 = st0 * wo[0][3]; p4 = st0 * wo[0][4]; p5 = st0 * wo[0][5];
        p0 = fmaf(st1, wo[1][0], p0); p1 = fmaf(st1, wo[1][1], p1);
        p2 = fmaf(st1, wo[1][2], p2); p3 = fmaf(st1, wo[1][3], p3);
        p4 = fmaf(st1, wo[1][4], p4); p5 = fmaf(st1, wo[1][5], p5);
        p0 = fmaf(st2, wo[2][0], p0); p1 = fmaf(st2, wo[2][1], p1);
        p2 = fmaf(st2, wo[2][2], p2); p3 = fmaf(st2, wo[2][3], p3);
        p4 = fmaf(st2, wo[2][4], p4); p5 = fmaf(st2, wo[2][5], p5);
        p0 = fmaf(st3, wo[3][0], p0); p1 = fmaf(st3, wo[3][1], p1);
        p2 = fmaf(st3, wo[3][2], p2); p3 = fmaf(st3, wo[3][3], p3);
        p4 = fmaf(st3, wo[3][4], p4); p5 = fmaf(st3, wo[3][5], p5);
        // 8-lane (within-head) butterfly reduce
#pragma unroll
        for (int o = 1; o < 8; o <<= 1) {
            p0 += __shfl_xor_sync(FULLMASK, p0, o);
            p1 += __shfl_xor_sync(FULLMASK, p1, o);
            p2 += __shfl_xor_sync(FULLMASK, p2, o);
            p3 += __shfl_xor_sync(FULLMASK, p3, o);
            p4 += __shfl_xor_sync(FULLMASK, p4, o);
            p5 += __shfl_xor_sync(FULLMASK, p5, o);
        }
        // lane g<6 stores head-sum for d=g
        float pv = (g == 0) ? p0 : (g == 1) ? p1 : (g == 2) ? p2
                 : (g == 3) ? p3 : (g == 4) ? p4 : p5;
        if (g < 6) *pw = pv;
        pw += 96;

        // rotate state / scales / inputs
        w0 = nw0; w1 = nw1; w2 = nw2; w3 = nw3;
        rnA = rnB; rnB = rn;
        xp = xn;
#pragma unroll
        for (int d = 0; d < Dd; ++d) cx[d] = nx[d];
    }
}

// ---------------------------------------------------------------------------
// Phase 2: combine — y[row,d] = x[row,d] + b_out[d] + sum_{16 heads} part
// One thread per output element (393216). ~37 MB traffic.
// ---------------------------------------------------------------------------
__global__ void __launch_bounds__(256) combine_kernel(
    const float* __restrict__ x,
    const float* __restrict__ b_out,
    float* __restrict__ y)
{
    const int e   = blockIdx.x * blockDim.x + threadIdx.x;  // 0..393215
    const int row = e / 6;              // chain*256 + t
    const int d   = e - row * 6;

    float acc = __ldg(b_out + d);
    const float* pp = g_part + (size_t)row * 96 + d;
#pragma unroll
    for (int j = 0; j < 16; ++j) acc += pp[j * 6];

    const int c = row >> 8;
    const int t = row & (Ss - 1);
    const int b = c >> 4;
    const int n = c & (Nn - 1);
    const size_t off = (((size_t)b * Ss + t) * Nn + n) * Dd + d;
    y[off] = __ldg(x + off) + acc;
}

extern "C" void kernel_launch(void* const* d_in, const int* in_sizes, int n_in,
                              void* d_out, int out_size) {
    const float* x     = (const float*)d_in[0];
    const float* W_in  = (const float*)d_in[1];
    const float* b_in  = (const float*)d_in[2];
    const float* W_out = (const float*)d_in[3];
    const float* b_out = (const float*)d_in[4];
    float* y = (float*)d_out;

    // Phase 1: recurrence + fused projection (1024 warps)
    rotor_rnn_kernel<<<128, 256>>>(x, W_in, b_in, W_out);
    // Phase 2: tiny combine (65536 rows x 6)
    combine_kernel<<<1536, 256>>>(x, b_out, y);
}